// round 5
// baseline (speedup 1.0000x reference)
#include <cuda_runtime.h>
#include <math.h>

// Problem constants (fixed by the reference setup_inputs)
#define BB 4
#define HH 12
#define SS 2048
#define DD 768
#define DKK 64
#define MM (BB * SS)   // 8192

// Scratch in static device memory (allocation-guard safe).
// Layout: [B, H, S, DK] fp32
__device__ float g_Q[BB * HH * SS * DKK];
__device__ float g_K[BB * HH * SS * DKK];
__device__ float g_V[BB * HH * SS * DKK];
__device__ float g_O[BB * HH * SS * DKK];

// ---------------------------------------------------------------------------
// Projection GEMM: out = X[8192,768] @ W[768,768] + b, scattered to [B,H,S,DK]
// with optional RoPE in the epilogue. which: 0->g_Q, 1->g_K, 2->g_V.
// ---------------------------------------------------------------------------
template <bool ROPE>
__global__ void proj_kernel(const float* __restrict__ X,
                            const float* __restrict__ W,
                            const float* __restrict__ bias,
                            int which)
{
    __shared__ float As[16][65];
    __shared__ float Bs[16][64];

    const int tid = threadIdx.x;
    const int ty = tid >> 4;       // 0..15
    const int tx = tid & 15;       // 0..15
    const int m0 = blockIdx.y * 64;
    const int n0 = blockIdx.x * 64;

    float acc[4][4] = {};

    const int arow  = tid >> 2;          // 0..63
    const int acol4 = (tid & 3) << 2;    // 0,4,8,12
    const int brow  = tid >> 4;          // 0..15
    const int bcol4 = (tid & 15) << 2;   // 0..60

    for (int k0 = 0; k0 < DD; k0 += 16) {
        float4 av = *reinterpret_cast<const float4*>(
            X + (size_t)(m0 + arow) * DD + (k0 + acol4));
        As[acol4 + 0][arow] = av.x;
        As[acol4 + 1][arow] = av.y;
        As[acol4 + 2][arow] = av.z;
        As[acol4 + 3][arow] = av.w;

        float4 bv = *reinterpret_cast<const float4*>(
            W + (size_t)(k0 + brow) * DD + (n0 + bcol4));
        *reinterpret_cast<float4*>(&Bs[brow][bcol4]) = bv;

        __syncthreads();

        #pragma unroll
        for (int kk = 0; kk < 16; kk++) {
            float a[4], b[4];
            #pragma unroll
            for (int i = 0; i < 4; i++) a[i] = As[kk][ty * 4 + i];
            #pragma unroll
            for (int j = 0; j < 4; j++) b[j] = Bs[kk][tx * 4 + j];
            #pragma unroll
            for (int i = 0; i < 4; i++)
                #pragma unroll
                for (int j = 0; j < 4; j++)
                    acc[i][j] += a[i] * b[j];
        }
        __syncthreads();
    }

    float* dst = (which == 0) ? g_Q : (which == 1) ? g_K : g_V;

    #pragma unroll
    for (int i = 0; i < 4; i++) {
        const int m = m0 + ty * 4 + i;
        const int b = m >> 11;         // / SS
        const int s = m & (SS - 1);
        float vals[4];
        #pragma unroll
        for (int j = 0; j < 4; j++)
            vals[j] = acc[i][j] + bias[n0 + tx * 4 + j];

        if (ROPE) {
            #pragma unroll
            for (int jp = 0; jp < 4; jp += 2) {
                const int c  = n0 + tx * 4 + jp;   // even, pair inside head
                const int d0 = c & 63;             // even index within head
                const float theta = expf(-(float)d0 * (9.210340371976184f / 64.0f));
                const float ang = (float)s * theta;
                const float cv = cosf(ang);
                const float sv = sinf(ang);
                const float x = vals[jp];
                const float y = vals[jp + 1];
                vals[jp]     = x * cv - y * sv;
                vals[jp + 1] = y * cv + x * sv;
            }
        }

        #pragma unroll
        for (int j = 0; j < 4; j++) {
            const int c = n0 + tx * 4 + j;
            const int h = c >> 6;
            const int d = c & 63;
            dst[(((size_t)(b * HH + h) * SS + s) << 6) + d] = vals[j];
        }
    }
}

// ---------------------------------------------------------------------------
// Flash attention: per (b, h, 64-row q tile). 256 threads, online softmax.
// Q, K, P stored TRANSPOSED in smem ([d][row], pad 68) so every inner-loop
// operand is one LDS.128. V row-major. Mask is 4-byte bool.
// ---------------------------------------------------------------------------
#define PADR 68
#define ATTN_SMEM (4 * 64 * PADR * 4 + 64 * 64)   // 73728

__global__ void attn_kernel(const unsigned int* __restrict__ mask32)
{
    extern __shared__ char sm_raw[];
    float (*QsT)[PADR]         = reinterpret_cast<float (*)[PADR]>(sm_raw);
    float (*KsT)[PADR]         = reinterpret_cast<float (*)[PADR]>(sm_raw + 17408);
    float (*Vs)[PADR]          = reinterpret_cast<float (*)[PADR]>(sm_raw + 34816);
    float (*PsT)[PADR]         = reinterpret_cast<float (*)[PADR]>(sm_raw + 52224);
    unsigned char (*Msk)[64]   = reinterpret_cast<unsigned char (*)[64]>(sm_raw + 69632);

    const int tid = threadIdx.x;
    const int ty = tid >> 4;   // row group 0..15 -> rows ty*4..+3
    const int tx = tid & 15;   // col group 0..15 -> cols tx*4..+3
    const int q0 = blockIdx.x * 64;
    const int h  = blockIdx.y;
    const int b  = blockIdx.z;

    const size_t base = (size_t)(b * HH + h) * SS * DKK;
    const float* Qg = g_Q + base;
    const float* Kg = g_K + base;
    const float* Vg = g_V + base;

    // Load Q tile transposed: QsT[d][q]
    #pragma unroll
    for (int p = 0; p < 4; p++) {
        const int chunk = p * 256 + tid;
        const int row = chunk & 63;           // q row
        const int d4  = (chunk >> 6) << 2;    // 0,4,...,60
        float4 v = *reinterpret_cast<const float4*>(Qg + (size_t)(q0 + row) * DKK + d4);
        QsT[d4 + 0][row] = v.x; QsT[d4 + 1][row] = v.y;
        QsT[d4 + 2][row] = v.z; QsT[d4 + 3][row] = v.w;
    }

    float m_i[4], l_i[4], o[4][4];
    #pragma unroll
    for (int i = 0; i < 4; i++) {
        m_i[i] = -INFINITY;
        l_i[i] = 0.0f;
        #pragma unroll
        for (int j = 0; j < 4; j++) o[i][j] = 0.0f;
    }

    const size_t mask_row_base = (size_t)b * SS + q0;  // mask[b,0,q,:]

    for (int k0 = 0; k0 < SS; k0 += 64) {
        // K tile transposed: KsT[d][key]
        #pragma unroll
        for (int p = 0; p < 4; p++) {
            const int chunk = p * 256 + tid;
            const int row = chunk & 63;
            const int d4  = (chunk >> 6) << 2;
            float4 kv = *reinterpret_cast<const float4*>(Kg + (size_t)(k0 + row) * DKK + d4);
            KsT[d4 + 0][row] = kv.x; KsT[d4 + 1][row] = kv.y;
            KsT[d4 + 2][row] = kv.z; KsT[d4 + 3][row] = kv.w;
        }
        // V tile row-major + mask tile (4-byte -> byte)
        #pragma unroll
        for (int p = 0; p < 4; p++) {
            const int chunk = p * 256 + tid;
            const int r  = chunk >> 4;
            const int c4 = (chunk & 15) << 2;
            float4 vv = *reinterpret_cast<const float4*>(Vg + (size_t)(k0 + r) * DKK + c4);
            *reinterpret_cast<float4*>(&Vs[r][c4]) = vv;
            uint4 mv = *reinterpret_cast<const uint4*>(
                mask32 + (mask_row_base + r) * SS + k0 + c4);
            Msk[r][c4 + 0] = (mv.x != 0u);
            Msk[r][c4 + 1] = (mv.y != 0u);
            Msk[r][c4 + 2] = (mv.z != 0u);
            Msk[r][c4 + 3] = (mv.w != 0u);
        }
        __syncthreads();

        // S = Q @ K^T : all operands via LDS.128
        float sv[4][4] = {};
        #pragma unroll 8
        for (int kk = 0; kk < 64; kk++) {
            float4 a4 = *reinterpret_cast<const float4*>(&QsT[kk][ty * 4]);
            float4 k4 = *reinterpret_cast<const float4*>(&KsT[kk][tx * 4]);
            const float a[4] = {a4.x, a4.y, a4.z, a4.w};
            const float kc[4] = {k4.x, k4.y, k4.z, k4.w};
            #pragma unroll
            for (int i = 0; i < 4; i++)
                #pragma unroll
                for (int j = 0; j < 4; j++)
                    sv[i][j] += a[i] * kc[j];
        }

        // scale + mask
        #pragma unroll
        for (int i = 0; i < 4; i++)
            #pragma unroll
            for (int j = 0; j < 4; j++) {
                float s = sv[i][j] * 0.125f;
                if (!Msk[ty * 4 + i][tx * 4 + j]) s = -1e9f;
                sv[i][j] = s;
            }

        // Online softmax update
        #pragma unroll
        for (int i = 0; i < 4; i++) {
            float mt = fmaxf(fmaxf(sv[i][0], sv[i][1]), fmaxf(sv[i][2], sv[i][3]));
            #pragma unroll
            for (int off = 8; off > 0; off >>= 1)
                mt = fmaxf(mt, __shfl_xor_sync(0xffffffffu, mt, off));
            const float mnew = fmaxf(m_i[i], mt);
            float lt = 0.0f;
            #pragma unroll
            for (int j = 0; j < 4; j++) {
                sv[i][j] = __expf(sv[i][j] - mnew);
                lt += sv[i][j];
            }
            #pragma unroll
            for (int off = 8; off > 0; off >>= 1)
                lt += __shfl_xor_sync(0xffffffffu, lt, off);
            const float corr = __expf(m_i[i] - mnew);
            l_i[i] = l_i[i] * corr + lt;
            m_i[i] = mnew;
            #pragma unroll
            for (int j = 0; j < 4; j++) o[i][j] *= corr;
        }

        // P tile -> smem TRANSPOSED: PsT[key][q]; one float4 per j
        #pragma unroll
        for (int j = 0; j < 4; j++) {
            float4 pv = make_float4(sv[0][j], sv[1][j], sv[2][j], sv[3][j]);
            *reinterpret_cast<float4*>(&PsT[tx * 4 + j][ty * 4]) = pv;
        }
        __syncthreads();

        // O += P @ V : all operands via LDS.128
        #pragma unroll 8
        for (int kk = 0; kk < 64; kk++) {
            float4 p4 = *reinterpret_cast<const float4*>(&PsT[kk][ty * 4]);
            float4 v4 = *reinterpret_cast<const float4*>(&Vs[kk][tx * 4]);
            const float p[4] = {p4.x, p4.y, p4.z, p4.w};
            const float vr[4] = {v4.x, v4.y, v4.z, v4.w};
            #pragma unroll
            for (int i = 0; i < 4; i++)
                #pragma unroll
                for (int j = 0; j < 4; j++)
                    o[i][j] += p[i] * vr[j];
        }
        __syncthreads();  // before next tile load overwrites KsT/Vs/Msk/PsT
    }

    // Normalize and write out
    #pragma unroll
    for (int i = 0; i < 4; i++) {
        const float inv = 1.0f / l_i[i];
        #pragma unroll
        for (int j = 0; j < 4; j++)
            g_O[base + (size_t)(q0 + ty * 4 + i) * DKK + tx * 4 + j] = o[i][j] * inv;
    }
}

// ---------------------------------------------------------------------------
// Output projection: out[8192,768] = gather(g_O as [M, D]) @ Wo + bo
// ---------------------------------------------------------------------------
__global__ void outproj_kernel(const float* __restrict__ W,
                               const float* __restrict__ bias,
                               float* __restrict__ out)
{
    __shared__ float As[16][65];
    __shared__ float Bs[16][64];

    const int tid = threadIdx.x;
    const int ty = tid >> 4;
    const int tx = tid & 15;
    const int m0 = blockIdx.y * 64;
    const int n0 = blockIdx.x * 64;

    float acc[4][4] = {};

    const int arow  = tid >> 2;
    const int acol4 = (tid & 3) << 2;
    const int brow  = tid >> 4;
    const int bcol4 = (tid & 15) << 2;

    const int gm = m0 + arow;
    const int ab = gm >> 11;
    const int as = gm & (SS - 1);

    for (int k0 = 0; k0 < DD; k0 += 16) {
        const int gk = k0 + acol4;
        const int ah = gk >> 6;
        const int ad = gk & 63;
        float4 av = *reinterpret_cast<const float4*>(
            g_O + (((size_t)(ab * HH + ah) * SS + as) << 6) + ad);
        As[acol4 + 0][arow] = av.x;
        As[acol4 + 1][arow] = av.y;
        As[acol4 + 2][arow] = av.z;
        As[acol4 + 3][arow] = av.w;

        float4 bv = *reinterpret_cast<const float4*>(
            W + (size_t)(k0 + brow) * DD + (n0 + bcol4));
        *reinterpret_cast<float4*>(&Bs[brow][bcol4]) = bv;

        __syncthreads();

        #pragma unroll
        for (int kk = 0; kk < 16; kk++) {
            float a[4], b[4];
            #pragma unroll
            for (int i = 0; i < 4; i++) a[i] = As[kk][ty * 4 + i];
            #pragma unroll
            for (int j = 0; j < 4; j++) b[j] = Bs[kk][tx * 4 + j];
            #pragma unroll
            for (int i = 0; i < 4; i++)
                #pragma unroll
                for (int j = 0; j < 4; j++)
                    acc[i][j] += a[i] * b[j];
        }
        __syncthreads();
    }

    #pragma unroll
    for (int i = 0; i < 4; i++) {
        const int m = m0 + ty * 4 + i;
        #pragma unroll
        for (int j = 0; j < 4; j++) {
            const int c = n0 + tx * 4 + j;
            out[(size_t)m * DD + c] = acc[i][j] + bias[c];
        }
    }
}

// ---------------------------------------------------------------------------
extern "C" void kernel_launch(void* const* d_in, const int* in_sizes, int n_in,
                              void* d_out, int out_size)
{
    (void)in_sizes; (void)n_in; (void)out_size;

    const float* query = (const float*)d_in[0];
    const float* key   = (const float*)d_in[1];
    const float* value = (const float*)d_in[2];
    const unsigned int* mask = (const unsigned int*)d_in[3];
    const float* Wq = (const float*)d_in[4];
    const float* bq = (const float*)d_in[5];
    const float* Wk = (const float*)d_in[6];
    const float* bk = (const float*)d_in[7];
    const float* Wv = (const float*)d_in[8];
    const float* bv = (const float*)d_in[9];
    const float* Wo = (const float*)d_in[10];
    const float* bo = (const float*)d_in[11];
    float* out = (float*)d_out;

    static bool attr_set = false;
    if (!attr_set) {
        cudaFuncSetAttribute(attn_kernel,
                             cudaFuncAttributeMaxDynamicSharedMemorySize, ATTN_SMEM);
        attr_set = true;
    }

    dim3 gemm_grid(DD / 64, MM / 64);  // (12, 128)
    proj_kernel<true ><<<gemm_grid, 256>>>(query, Wq, bq, 0);
    proj_kernel<true ><<<gemm_grid, 256>>>(key,   Wk, bk, 1);
    proj_kernel<false><<<gemm_grid, 256>>>(value, Wv, bv, 2);

    dim3 attn_grid(SS / 64, HH, BB);   // (32, 12, 4)
    attn_kernel<<<attn_grid, 256, ATTN_SMEM>>>(mask);

    outproj_kernel<<<gemm_grid, 256>>>(Wo, bo, out);
}

// round 6
// speedup vs baseline: 1.0738x; 1.0738x over previous
#include <cuda_runtime.h>
#include <math.h>

#define BB 4
#define HH 12
#define SS 2048
#define DD 768
#define DKK 64
#define MM (BB * SS)   // 8192

// Scratch [B, H, S, DK] fp32
__device__ float g_Q[BB * HH * SS * DKK];
__device__ float g_K[BB * HH * SS * DKK];
__device__ float g_V[BB * HH * SS * DKK];
__device__ float g_O[BB * HH * SS * DKK];

// ---------------------------------------------------------------------------
// Projection GEMM: 128x64 block tile, 256 threads, 8x4 microtile, k-step 16.
// A stored transposed in smem ([k][m], pad 132). RoPE epilogue optional.
// ---------------------------------------------------------------------------
template <bool ROPE>
__global__ void proj_kernel(const float* __restrict__ X,
                            const float* __restrict__ W,
                            const float* __restrict__ bias,
                            int which)
{
    __shared__ float As[16][132];
    __shared__ float Bs[16][64];

    const int tid = threadIdx.x;
    const int ty = tid >> 4;       // 0..15 -> rows ty*8..+7
    const int tx = tid & 15;       // 0..15 -> cols tx*4..+3
    const int m0 = blockIdx.y * 128;
    const int n0 = blockIdx.x * 64;

    float acc[8][4] = {};

    // A loader: 2 float4 per thread per k-step (coalesced global reads)
    const int arow  = tid >> 2;          // 0..63
    const int acol4 = (tid & 3) << 2;    // 0,4,8,12
    // B loader: 1 float4 per thread
    const int brow  = tid >> 4;
    const int bcol4 = (tid & 15) << 2;

    for (int k0 = 0; k0 < DD; k0 += 16) {
        #pragma unroll
        for (int p = 0; p < 2; p++) {
            const int row = p * 64 + arow;
            float4 av = *reinterpret_cast<const float4*>(
                X + (size_t)(m0 + row) * DD + (k0 + acol4));
            As[acol4 + 0][row] = av.x;
            As[acol4 + 1][row] = av.y;
            As[acol4 + 2][row] = av.z;
            As[acol4 + 3][row] = av.w;
        }
        float4 bv = *reinterpret_cast<const float4*>(
            W + (size_t)(k0 + brow) * DD + (n0 + bcol4));
        *reinterpret_cast<float4*>(&Bs[brow][bcol4]) = bv;

        __syncthreads();

        #pragma unroll
        for (int kk = 0; kk < 16; kk++) {
            float4 a0 = *reinterpret_cast<const float4*>(&As[kk][ty * 8]);
            float4 a1 = *reinterpret_cast<const float4*>(&As[kk][ty * 8 + 4]);
            float4 b4 = *reinterpret_cast<const float4*>(&Bs[kk][tx * 4]);
            const float a[8] = {a0.x, a0.y, a0.z, a0.w, a1.x, a1.y, a1.z, a1.w};
            const float b[4] = {b4.x, b4.y, b4.z, b4.w};
            #pragma unroll
            for (int i = 0; i < 8; i++)
                #pragma unroll
                for (int j = 0; j < 4; j++)
                    acc[i][j] += a[i] * b[j];
        }
        __syncthreads();
    }

    float* dst = (which == 0) ? g_Q : (which == 1) ? g_K : g_V;
    const int h  = (n0 + tx * 4) >> 6;   // same head for all 4 j
    const int d0c = (n0 + tx * 4) & 63;

    #pragma unroll
    for (int i = 0; i < 8; i++) {
        const int m = m0 + ty * 8 + i;
        const int b = m >> 11;
        const int s = m & (SS - 1);
        float vals[4];
        #pragma unroll
        for (int j = 0; j < 4; j++)
            vals[j] = acc[i][j] + bias[n0 + tx * 4 + j];

        if (ROPE) {
            #pragma unroll
            for (int jp = 0; jp < 4; jp += 2) {
                const int d0 = d0c + jp;   // even index within head
                const float theta = expf(-(float)d0 * (9.210340371976184f / 64.0f));
                const float ang = (float)s * theta;
                const float cv = cosf(ang);
                const float sv = sinf(ang);
                const float x = vals[jp];
                const float y = vals[jp + 1];
                vals[jp]     = x * cv - y * sv;
                vals[jp + 1] = y * cv + x * sv;
            }
        }
        float4 o4 = make_float4(vals[0], vals[1], vals[2], vals[3]);
        *reinterpret_cast<float4*>(
            dst + (((size_t)(b * HH + h) * SS + s) << 6) + d0c) = o4;
    }
}

// ---------------------------------------------------------------------------
// Flash attention: 128 q-rows x 64 k-cols per tile, 256 threads, 8x4 microtile.
// Q/K/P transposed in smem; V row-major; mask read straight from global.
// ---------------------------------------------------------------------------
#define ATTN_SMEM 102400

__global__ void attn_kernel(const unsigned int* __restrict__ mask32)
{
    extern __shared__ char sm_raw[];
    float (*QsT)[132] = reinterpret_cast<float (*)[132]>(sm_raw);            // [d][q] 33792B
    float (*KsT)[68]  = reinterpret_cast<float (*)[68]>(sm_raw + 33792);     // [d][k] 17408B
    float (*Vs)[68]   = reinterpret_cast<float (*)[68]>(sm_raw + 51200);     // [k][d] 17408B
    float (*PsT)[132] = reinterpret_cast<float (*)[132]>(sm_raw + 68608);    // [k][q] 33792B

    const int tid = threadIdx.x;
    const int ty = tid >> 4;   // 0..15 -> q rows ty*8..+7
    const int tx = tid & 15;   // 0..15 -> k cols tx*4..+3
    const int q0 = blockIdx.x * 128;
    const int h  = blockIdx.y;
    const int b  = blockIdx.z;

    const size_t base = (size_t)(b * HH + h) * SS * DKK;
    const float* Qg = g_Q + base;
    const float* Kg = g_K + base;
    const float* Vg = g_V + base;

    // Q tile transposed: QsT[d][q], 128 rows x 64 d
    #pragma unroll
    for (int p = 0; p < 8; p++) {
        const int chunk = p * 256 + tid;
        const int row = chunk & 127;
        const int d4  = (chunk >> 7) << 2;
        float4 v = *reinterpret_cast<const float4*>(Qg + (size_t)(q0 + row) * DKK + d4);
        QsT[d4 + 0][row] = v.x; QsT[d4 + 1][row] = v.y;
        QsT[d4 + 2][row] = v.z; QsT[d4 + 3][row] = v.w;
    }

    float m_i[8], l_i[8], o[8][4];
    #pragma unroll
    for (int i = 0; i < 8; i++) {
        m_i[i] = -INFINITY;
        l_i[i] = 0.0f;
        #pragma unroll
        for (int j = 0; j < 4; j++) o[i][j] = 0.0f;
    }

    const size_t mrow0 = (size_t)b * SS + q0;  // mask[b,0,q,:] row base

    for (int k0 = 0; k0 < SS; k0 += 64) {
        // K tile transposed: KsT[d][key]
        #pragma unroll
        for (int p = 0; p < 4; p++) {
            const int chunk = p * 256 + tid;
            const int row = chunk & 63;
            const int d4  = (chunk >> 6) << 2;
            float4 kv = *reinterpret_cast<const float4*>(Kg + (size_t)(k0 + row) * DKK + d4);
            KsT[d4 + 0][row] = kv.x; KsT[d4 + 1][row] = kv.y;
            KsT[d4 + 2][row] = kv.z; KsT[d4 + 3][row] = kv.w;
        }
        // V tile row-major
        #pragma unroll
        for (int p = 0; p < 4; p++) {
            const int chunk = p * 256 + tid;
            const int r  = chunk >> 4;
            const int c4 = (chunk & 15) << 2;
            float4 vv = *reinterpret_cast<const float4*>(Vg + (size_t)(k0 + r) * DKK + c4);
            *reinterpret_cast<float4*>(&Vs[r][c4]) = vv;
        }
        __syncthreads();

        // S = Q @ K^T
        float sv[8][4] = {};
        #pragma unroll 8
        for (int kk = 0; kk < 64; kk++) {
            float4 a0 = *reinterpret_cast<const float4*>(&QsT[kk][ty * 8]);
            float4 a1 = *reinterpret_cast<const float4*>(&QsT[kk][ty * 8 + 4]);
            float4 k4 = *reinterpret_cast<const float4*>(&KsT[kk][tx * 4]);
            const float a[8] = {a0.x, a0.y, a0.z, a0.w, a1.x, a1.y, a1.z, a1.w};
            const float kc[4] = {k4.x, k4.y, k4.z, k4.w};
            #pragma unroll
            for (int i = 0; i < 8; i++)
                #pragma unroll
                for (int j = 0; j < 4; j++)
                    sv[i][j] += a[i] * kc[j];
        }

        // scale + mask (read straight from global; coalesced uint4 per row)
        #pragma unroll
        for (int i = 0; i < 8; i++) {
            uint4 mv = *reinterpret_cast<const uint4*>(
                mask32 + (mrow0 + ty * 8 + i) * SS + k0 + tx * 4);
            float s0 = sv[i][0] * 0.125f;
            float s1 = sv[i][1] * 0.125f;
            float s2 = sv[i][2] * 0.125f;
            float s3 = sv[i][3] * 0.125f;
            sv[i][0] = mv.x ? s0 : -1e9f;
            sv[i][1] = mv.y ? s1 : -1e9f;
            sv[i][2] = mv.z ? s2 : -1e9f;
            sv[i][3] = mv.w ? s3 : -1e9f;
        }

        // Online softmax update (row spans 16 lanes: xor 8,4,2,1)
        #pragma unroll
        for (int i = 0; i < 8; i++) {
            float mt = fmaxf(fmaxf(sv[i][0], sv[i][1]), fmaxf(sv[i][2], sv[i][3]));
            #pragma unroll
            for (int off = 8; off > 0; off >>= 1)
                mt = fmaxf(mt, __shfl_xor_sync(0xffffffffu, mt, off));
            const float mnew = fmaxf(m_i[i], mt);
            float lt = 0.0f;
            #pragma unroll
            for (int j = 0; j < 4; j++) {
                sv[i][j] = __expf(sv[i][j] - mnew);
                lt += sv[i][j];
            }
            #pragma unroll
            for (int off = 8; off > 0; off >>= 1)
                lt += __shfl_xor_sync(0xffffffffu, lt, off);
            const float corr = __expf(m_i[i] - mnew);
            l_i[i] = l_i[i] * corr + lt;
            m_i[i] = mnew;
            #pragma unroll
            for (int j = 0; j < 4; j++) o[i][j] *= corr;
        }

        // P -> smem transposed: PsT[key][q]
        #pragma unroll
        for (int j = 0; j < 4; j++) {
            float4 p0 = make_float4(sv[0][j], sv[1][j], sv[2][j], sv[3][j]);
            float4 p1 = make_float4(sv[4][j], sv[5][j], sv[6][j], sv[7][j]);
            *reinterpret_cast<float4*>(&PsT[tx * 4 + j][ty * 8])     = p0;
            *reinterpret_cast<float4*>(&PsT[tx * 4 + j][ty * 8 + 4]) = p1;
        }
        __syncthreads();

        // O += P @ V
        #pragma unroll 8
        for (int kk = 0; kk < 64; kk++) {
            float4 p0 = *reinterpret_cast<const float4*>(&PsT[kk][ty * 8]);
            float4 p1 = *reinterpret_cast<const float4*>(&PsT[kk][ty * 8 + 4]);
            float4 v4 = *reinterpret_cast<const float4*>(&Vs[kk][tx * 4]);
            const float p[8] = {p0.x, p0.y, p0.z, p0.w, p1.x, p1.y, p1.z, p1.w};
            const float vr[4] = {v4.x, v4.y, v4.z, v4.w};
            #pragma unroll
            for (int i = 0; i < 8; i++)
                #pragma unroll
                for (int j = 0; j < 4; j++)
                    o[i][j] += p[i] * vr[j];
        }
        __syncthreads();
    }

    // Normalize and write out (float4 per row)
    #pragma unroll
    for (int i = 0; i < 8; i++) {
        const float inv = 1.0f / l_i[i];
        float4 o4 = make_float4(o[i][0] * inv, o[i][1] * inv,
                                o[i][2] * inv, o[i][3] * inv);
        *reinterpret_cast<float4*>(
            g_O + base + (size_t)(q0 + ty * 8 + i) * DKK + tx * 4) = o4;
    }
}

// ---------------------------------------------------------------------------
// Output projection: 128x64 tile, 8x4 microtile, gather from g_O
// ---------------------------------------------------------------------------
__global__ void outproj_kernel(const float* __restrict__ W,
                               const float* __restrict__ bias,
                               float* __restrict__ out)
{
    __shared__ float As[16][132];
    __shared__ float Bs[16][64];

    const int tid = threadIdx.x;
    const int ty = tid >> 4;
    const int tx = tid & 15;
    const int m0 = blockIdx.y * 128;
    const int n0 = blockIdx.x * 64;

    float acc[8][4] = {};

    const int arow  = tid >> 2;
    const int acol4 = (tid & 3) << 2;
    const int brow  = tid >> 4;
    const int bcol4 = (tid & 15) << 2;

    for (int k0 = 0; k0 < DD; k0 += 16) {
        const int gk = k0 + acol4;
        const int ah = gk >> 6;
        const int ad = gk & 63;
        #pragma unroll
        for (int p = 0; p < 2; p++) {
            const int row = p * 64 + arow;
            const int gm = m0 + row;
            const int ab = gm >> 11;
            const int as = gm & (SS - 1);
            float4 av = *reinterpret_cast<const float4*>(
                g_O + (((size_t)(ab * HH + ah) * SS + as) << 6) + ad);
            As[acol4 + 0][row] = av.x;
            As[acol4 + 1][row] = av.y;
            As[acol4 + 2][row] = av.z;
            As[acol4 + 3][row] = av.w;
        }
        float4 bv = *reinterpret_cast<const float4*>(
            W + (size_t)(k0 + brow) * DD + (n0 + bcol4));
        *reinterpret_cast<float4*>(&Bs[brow][bcol4]) = bv;

        __syncthreads();

        #pragma unroll
        for (int kk = 0; kk < 16; kk++) {
            float4 a0 = *reinterpret_cast<const float4*>(&As[kk][ty * 8]);
            float4 a1 = *reinterpret_cast<const float4*>(&As[kk][ty * 8 + 4]);
            float4 b4 = *reinterpret_cast<const float4*>(&Bs[kk][tx * 4]);
            const float a[8] = {a0.x, a0.y, a0.z, a0.w, a1.x, a1.y, a1.z, a1.w};
            const float b[4] = {b4.x, b4.y, b4.z, b4.w};
            #pragma unroll
            for (int i = 0; i < 8; i++)
                #pragma unroll
                for (int j = 0; j < 4; j++)
                    acc[i][j] += a[i] * b[j];
        }
        __syncthreads();
    }

    const float4 b4 = *reinterpret_cast<const float4*>(bias + n0 + tx * 4);
    #pragma unroll
    for (int i = 0; i < 8; i++) {
        const int m = m0 + ty * 8 + i;
        float4 o4 = make_float4(acc[i][0] + b4.x, acc[i][1] + b4.y,
                                acc[i][2] + b4.z, acc[i][3] + b4.w);
        *reinterpret_cast<float4*>(out + (size_t)m * DD + n0 + tx * 4) = o4;
    }
}

// ---------------------------------------------------------------------------
extern "C" void kernel_launch(void* const* d_in, const int* in_sizes, int n_in,
                              void* d_out, int out_size)
{
    (void)in_sizes; (void)n_in; (void)out_size;

    const float* query = (const float*)d_in[0];
    const float* key   = (const float*)d_in[1];
    const float* value = (const float*)d_in[2];
    const unsigned int* mask = (const unsigned int*)d_in[3];
    const float* Wq = (const float*)d_in[4];
    const float* bq = (const float*)d_in[5];
    const float* Wk = (const float*)d_in[6];
    const float* bk = (const float*)d_in[7];
    const float* Wv = (const float*)d_in[8];
    const float* bv = (const float*)d_in[9];
    const float* Wo = (const float*)d_in[10];
    const float* bo = (const float*)d_in[11];
    float* out = (float*)d_out;

    static bool attr_set = false;
    if (!attr_set) {
        cudaFuncSetAttribute(attn_kernel,
                             cudaFuncAttributeMaxDynamicSharedMemorySize, ATTN_SMEM);
        attr_set = true;
    }

    dim3 gemm_grid(DD / 64, MM / 128);  // (12, 64)
    proj_kernel<true ><<<gemm_grid, 256>>>(query, Wq, bq, 0);
    proj_kernel<true ><<<gemm_grid, 256>>>(key,   Wk, bk, 1);
    proj_kernel<false><<<gemm_grid, 256>>>(value, Wv, bv, 2);

    dim3 attn_grid(SS / 128, HH, BB);   // (16, 12, 4)
    attn_kernel<<<attn_grid, 256, ATTN_SMEM>>>(mask);

    outproj_kernel<<<gemm_grid, 256>>>(Wo, bo, out);
}